// round 9
// baseline (speedup 1.0000x reference)
#include <cuda_runtime.h>
#include <math.h>

// Problem constants
#define Bq 128
#define Tq 160
#define Fq 512
#define Eq 64
#define Hq 1024
#define IN0q (Fq + Eq)   // 576

// -------------------- persistent scratch (device globals, no allocs) --------------------
__device__ float g_h0[Tq * Bq * Hq];   // layer-0 hidden per timestep  (84 MB)
__device__ float g_h1[Tq * Bq * Hq];   // layer-1 hidden per timestep  (84 MB)
__device__ float g_c0[Bq * Hq];        // layer-0 cell state (current)
__device__ float g_c1[Bq * Hq];        // layer-1 cell state (current)
__device__ unsigned char g_mask[Bq * Tq];  // canonical uint8 mask

__device__ __forceinline__ float sigmoidf_(float x) { return 1.0f / (1.0f + expf(-x)); }

// -------------------- mask dtype detection + normalization --------------------
// The harness may hand us the JAX bool mask as uint8 (1B), int32, or float32 (4B).
// Detection: over the first 4096 bytes, bytes at offsets == 1 (mod 4) are always
// zero for int32 0/1 (01 00 00 00) and float32 0.0/1.0 (00 00 80 3f), but are
// nonzero ~30% of the time for a dense uint8 Bernoulli(0.3) mask. Any nonzero
// sample => 1-byte layout.  (Buffer is >= Bq*Tq bytes in all cases, so the
// 4096-byte probe window never reads out of bounds.)
__global__ void mask_norm_kernel(const unsigned char* __restrict__ m_raw)
{
    __shared__ int s_is_u8;
    int tid = threadIdx.x;
    if (tid == 0) s_is_u8 = 0;
    __syncthreads();
    // probe: 1024 samples at byte offsets 4*i + 1
    for (int i = tid; i < 1024; i += blockDim.x) {
        if (m_raw[4 * i + 1] != 0) atomicOr(&s_is_u8, 1);
    }
    __syncthreads();
    const int is_u8 = s_is_u8;
    const unsigned int* m32 = reinterpret_cast<const unsigned int*>(m_raw);
    for (int i = tid; i < Bq * Tq; i += blockDim.x) {
        unsigned char v;
        if (is_u8) v = (m_raw[i] != 0) ? 1 : 0;
        else       v = (m32[i] != 0u) ? 1 : 0;   // works for int32 1 and float32 1.0f
        g_mask[i] = v;
    }
}

// Shared layout:
//   xs[b*33 + k]  : 64 b-rows x 32 k (pad 33 -> conflict-free LDS/STS)
//   ws[k*65 + n]  : 32 k-rows x 64 n (pad 65 -> conflict-free LDS/STS)
struct SmemT {
    float xs[64 * 33];
    float ws[32 * 65];
    float mu_s[64];
    unsigned char um_s[64];
};

// One GEMM phase: acc[b_i][gate] += x[b][k] * W[gate*H + j0 + jj][k]
// CTA tile: 64 b x (16 jj x 4 gates), K = kcols (multiple of 32).
// x source: either a global row-major array (base + b*stride + k), or the "label"
// segment built on the fly: use_mu ? mu[b]*W_tgt[k] + b_tgt[k] : emb[b][k].
__device__ __forceinline__ void gemm_phase(
    float (&acc)[8][4],
    const float* __restrict__ xbase, int xstride,
    int lab_mode,
    const float* __restrict__ emb_base, int emb_stride,
    const float* __restrict__ Wt, const float* __restrict__ bt,
    const float* __restrict__ W, int ldW, int kcols,
    int b0, int j0, int tid, int tx, int ty,
    SmemT* sm)
{
    const int ntiles = kcols >> 5;
    float xr[16], wr[16];

    auto load_tile = [&](int kt) {
        const int k0 = kt << 5;
#pragma unroll
        for (int r = 0; r < 16; ++r) {
            int idx = tid + (r << 7);       // 128 threads x 16 = 2048 elems
            int k = idx & 31;
            int q = idx >> 5;               // b for x, n for w
            int kg = k0 + k;
            float xv;
            if (!lab_mode) {
                xv = xbase[(b0 + q) * xstride + kg];
            } else {
                if (sm->um_s[q]) xv = fmaf(sm->mu_s[q], Wt[kg], bt[kg]);
                else             xv = emb_base[(b0 + q) * emb_stride + kg];
            }
            xr[r] = xv;
            int g = q >> 4, jj = q & 15;
            wr[r] = W[(g * Hq + j0 + jj) * ldW + kg];
        }
    };

    load_tile(0);
    for (int kt = 0; kt < ntiles; ++kt) {
        __syncthreads();
#pragma unroll
        for (int r = 0; r < 16; ++r) {
            int idx = tid + (r << 7);
            int k = idx & 31;
            int q = idx >> 5;
            sm->xs[q * 33 + k] = xr[r];
            sm->ws[k * 65 + q] = wr[r];
        }
        __syncthreads();
        if (kt + 1 < ntiles) load_tile(kt + 1);  // overlap next-tile loads with compute
#pragma unroll
        for (int k = 0; k < 32; ++k) {
            float xv[8];
#pragma unroll
            for (int i = 0; i < 8; ++i) xv[i] = sm->xs[(ty * 8 + i) * 33 + k];
#pragma unroll
            for (int g = 0; g < 4; ++g) {
                float wv = sm->ws[k * 65 + g * 16 + tx];
#pragma unroll
                for (int i = 0; i < 8; ++i) acc[i][g] = fmaf(xv[i], wv, acc[i][g]);
            }
        }
    }
}

// Fused epilogue: add biases, LSTM cell update, write c-state and h.
__device__ __forceinline__ void lstm_epilogue(
    float (&acc)[8][4],
    const float* __restrict__ b_ih, const float* __restrict__ b_hh,
    float* __restrict__ c_state, float* __restrict__ h_arr,
    int t, int b0, int j0, int tx, int ty)
{
    float bsum[4];
#pragma unroll
    for (int g = 0; g < 4; ++g) {
        int row = g * Hq + j0 + tx;
        bsum[g] = b_ih[row] + b_hh[row];
    }
    int j = j0 + tx;
#pragma unroll
    for (int i = 0; i < 8; ++i) {
        int bg = b0 + ty * 8 + i;
        float gi = acc[i][0] + bsum[0];
        float gf = acc[i][1] + bsum[1];
        float gg = acc[i][2] + bsum[2];
        float go = acc[i][3] + bsum[3];
        int cidx = bg * Hq + j;
        float cp = (t == 0) ? 0.0f : c_state[cidx];
        float c = sigmoidf_(gf) * cp + sigmoidf_(gi) * tanhf(gg);
        float h = sigmoidf_(go) * tanhf(c);
        c_state[cidx] = c;
        h_arr[(t * Bq + bg) * Hq + j] = h;
    }
}

// ----------------------------- layer-0 cell (one timestep) -----------------------------
__global__ void __launch_bounds__(128) cell0_kernel(
    const float* __restrict__ feat, const float* __restrict__ emb,
    const float* __restrict__ W_ih0, const float* __restrict__ W_hh0,
    const float* __restrict__ b_ih0, const float* __restrict__ b_hh0,
    const float* __restrict__ W_tgt, const float* __restrict__ b_tgt,
    const float* __restrict__ mu_w, const float* __restrict__ mu_b, int t)
{
    __shared__ SmemT sm;
    int tid = threadIdx.x;
    int tx = tid & 15, ty = tid >> 4;
    int jb = blockIdx.x & 63;
    int b0 = (blockIdx.x >> 6) * 64;
    int j0 = jb * 16;

    // use-mu flags for this CTA's 64 batch rows (canonical uint8 mask)
    if (tid < 64) {
        bool um = (t > 0) && (g_mask[(b0 + tid) * Tq + t] != 0);
        sm.um_s[tid] = um ? 1 : 0;
        // NOTE: no zero-init of mu_s here — for t>0 all 64 entries are written
        // by the warp loop below (before the single __syncthreads), and for
        // t==0 mu_s is never read (um_s==0). A concurrent zero-init raced with
        // the warp writes and corrupted the fed-back mu values.
    }

    // mu[b] from previous step's hidden state: hp[b, 2h+l] = h_l[b][h]
    if (t > 0) {
        int wid = tid >> 5, lane = tid & 31;
        const float2* mw2 = reinterpret_cast<const float2*>(mu_w);
        for (int bi = wid; bi < 64; bi += 4) {
            int bg = b0 + bi;
            const float* h0r = g_h0 + ((t - 1) * Bq + bg) * Hq;
            const float* h1r = g_h1 + ((t - 1) * Bq + bg) * Hq;
            float p = 0.0f;
            for (int h = lane; h < Hq; h += 32) {
                float2 m = mw2[h];
                p = fmaf(h0r[h], m.x, p);
                p = fmaf(h1r[h], m.y, p);
            }
#pragma unroll
            for (int o = 16; o; o >>= 1) p += __shfl_xor_sync(0xffffffffu, p, o);
            if (lane == 0) sm.mu_s[bi] = p + mu_b[0];
        }
    }
    __syncthreads();

    float acc[8][4];
#pragma unroll
    for (int i = 0; i < 8; ++i)
#pragma unroll
        for (int g = 0; g < 4; ++g) acc[i][g] = 0.0f;

    // phase A1: feat part  (K = 512), x[b][k] = feat[b][t][k]
    gemm_phase(acc, feat + t * Fq, Tq * Fq, 0, nullptr, 0, nullptr, nullptr,
               W_ih0, IN0q, Fq, b0, j0, tid, tx, ty, &sm);
    // phase A2: label part (K = 64), built on the fly from mask/mu/W_tgt/b_tgt or labels
    gemm_phase(acc, nullptr, 0, 1, emb + t * Eq, Tq * Eq, W_tgt, b_tgt,
               W_ih0 + Fq, IN0q, Eq, b0, j0, tid, tx, ty, &sm);
    // phase B: recurrent part (K = 1024), x = h0(t-1); h0(-1) = 0 -> skip
    if (t > 0)
        gemm_phase(acc, g_h0 + (t - 1) * Bq * Hq, Hq, 0, nullptr, 0, nullptr, nullptr,
                   W_hh0, Hq, Hq, b0, j0, tid, tx, ty, &sm);

    lstm_epilogue(acc, b_ih0, b_hh0, g_c0, g_h0, t, b0, j0, tx, ty);
}

// ----------------------------- layer-1 cell (one timestep) -----------------------------
__global__ void __launch_bounds__(128) cell1_kernel(
    const float* __restrict__ W_ih1, const float* __restrict__ W_hh1,
    const float* __restrict__ b_ih1, const float* __restrict__ b_hh1, int t)
{
    __shared__ SmemT sm;
    int tid = threadIdx.x;
    int tx = tid & 15, ty = tid >> 4;
    int jb = blockIdx.x & 63;
    int b0 = (blockIdx.x >> 6) * 64;
    int j0 = jb * 16;

    float acc[8][4];
#pragma unroll
    for (int i = 0; i < 8; ++i)
#pragma unroll
        for (int g = 0; g < 4; ++g) acc[i][g] = 0.0f;

    // phase A: x = h0(t)  (just written by cell0 for this step)
    gemm_phase(acc, g_h0 + t * Bq * Hq, Hq, 0, nullptr, 0, nullptr, nullptr,
               W_ih1, Hq, Hq, b0, j0, tid, tx, ty, &sm);
    // phase B: x = h1(t-1)
    if (t > 0)
        gemm_phase(acc, g_h1 + (t - 1) * Bq * Hq, Hq, 0, nullptr, 0, nullptr, nullptr,
                   W_hh1, Hq, Hq, b0, j0, tid, tx, ty, &sm);

    lstm_epilogue(acc, b_ih1, b_hh1, g_c1, g_h1, t, b0, j0, tx, ty);
}

// -------------------- final outputs: mu/sigma for all (b, t) in parallel --------------------
__global__ void out_kernel(
    const float* __restrict__ mu_w, const float* __restrict__ mu_b,
    const float* __restrict__ sig_w, const float* __restrict__ sig_b,
    float* __restrict__ out)
{
    int t = blockIdx.x;
    int wid = threadIdx.x >> 5, lane = threadIdx.x & 31;
    const float2* mw2 = reinterpret_cast<const float2*>(mu_w);
    const float2* sw2 = reinterpret_cast<const float2*>(sig_w);
    for (int b = wid; b < Bq; b += 8) {
        const float* h0r = g_h0 + (t * Bq + b) * Hq;
        const float* h1r = g_h1 + (t * Bq + b) * Hq;
        float mp = 0.0f, sp = 0.0f;
        for (int h = lane; h < Hq; h += 32) {
            float a = h0r[h], c = h1r[h];
            float2 m = mw2[h];
            float2 s = sw2[h];
            mp = fmaf(a, m.x, fmaf(c, m.y, mp));
            sp = fmaf(a, s.x, fmaf(c, s.y, sp));
        }
#pragma unroll
        for (int o = 16; o; o >>= 1) {
            mp += __shfl_xor_sync(0xffffffffu, mp, o);
            sp += __shfl_xor_sync(0xffffffffu, sp, o);
        }
        if (lane == 0) {
            float mu = mp + mu_b[0];
            float sv = sp + sig_b[0];
            // stable softplus matching jax.nn.softplus
            float sig = fmaxf(sv, 0.0f) + log1pf(expf(-fabsf(sv)));
            out[(b * Tq + t) * 2 + 0] = mu;
            out[(b * Tq + t) * 2 + 1] = sig;
        }
    }
}

// ----------------------------------- launch -----------------------------------
extern "C" void kernel_launch(void* const* d_in, const int* in_sizes, int n_in,
                              void* d_out, int out_size)
{
    const float* feat  = (const float*)d_in[0];
    const float* emb   = (const float*)d_in[1];
    const unsigned char* mask_raw = (const unsigned char*)d_in[2];
    const float* W_ih0 = (const float*)d_in[3];
    const float* W_hh0 = (const float*)d_in[4];
    const float* b_ih0 = (const float*)d_in[5];
    const float* b_hh0 = (const float*)d_in[6];
    const float* W_ih1 = (const float*)d_in[7];
    const float* W_hh1 = (const float*)d_in[8];
    const float* b_ih1 = (const float*)d_in[9];
    const float* b_hh1 = (const float*)d_in[10];
    const float* W_tgt = (const float*)d_in[11];
    const float* b_tgt = (const float*)d_in[12];
    const float* mu_w  = (const float*)d_in[13];
    const float* mu_b  = (const float*)d_in[14];
    const float* sig_w = (const float*)d_in[15];
    const float* sig_b = (const float*)d_in[16];
    float* out = (float*)d_out;

    mask_norm_kernel<<<1, 1024>>>(mask_raw);
    for (int t = 0; t < Tq; ++t) {
        cell0_kernel<<<128, 128>>>(feat, emb, W_ih0, W_hh0, b_ih0, b_hh0,
                                   W_tgt, b_tgt, mu_w, mu_b, t);
        cell1_kernel<<<128, 128>>>(W_ih1, W_hh1, b_ih1, b_hh1, t);
    }
    out_kernel<<<Tq, 256>>>(mu_w, mu_b, sig_w, sig_b, out);
}

// round 10
// speedup vs baseline: 1.1093x; 1.1093x over previous
#include <cuda_runtime.h>
#include <cuda_bf16.h>
#include <math.h>

// Problem constants
#define Bq 128
#define Tq 160
#define Fq 512
#define Eq 64
#define Hq 1024
#define IN0q (Fq + Eq)   // 576

// ==================== persistent device scratch (no allocs) ====================
// Pre-split weights (hi/lo bf16), layout identical to fp32 originals.
__device__ __align__(256) __nv_bfloat16 g_WihH0[4 * Hq * IN0q];
__device__ __align__(256) __nv_bfloat16 g_WihL0[4 * Hq * IN0q];
__device__ __align__(256) __nv_bfloat16 g_WhhH0[4 * Hq * Hq];
__device__ __align__(256) __nv_bfloat16 g_WhhL0[4 * Hq * Hq];
__device__ __align__(256) __nv_bfloat16 g_WihH1[4 * Hq * Hq];
__device__ __align__(256) __nv_bfloat16 g_WihL1[4 * Hq * Hq];
__device__ __align__(256) __nv_bfloat16 g_WhhH1[4 * Hq * Hq];
__device__ __align__(256) __nv_bfloat16 g_WhhL1[4 * Hq * Hq];
// Pre-split features [B][T][F]
__device__ __align__(256) __nv_bfloat16 g_featH[Bq * Tq * Fq];
__device__ __align__(256) __nv_bfloat16 g_featL[Bq * Tq * Fq];
// Hidden states stored split [T][B][H]
__device__ __align__(256) __nv_bfloat16 g_h0h[Tq * Bq * Hq];
__device__ __align__(256) __nv_bfloat16 g_h0l[Tq * Bq * Hq];
__device__ __align__(256) __nv_bfloat16 g_h1h[Tq * Bq * Hq];
__device__ __align__(256) __nv_bfloat16 g_h1l[Tq * Bq * Hq];
// Cell states (fp32, current step)
__device__ float g_c0[Bq * Hq];
__device__ float g_c1[Bq * Hq];
// mu accumulation double buffer (parity = t&1) + canonical mask
__device__ float g_mu[2][Bq];
__device__ unsigned char g_mask[Bq * Tq];

__device__ __forceinline__ float sigmoidf_(float x) { return 1.0f / (1.0f + expf(-x)); }

__device__ __forceinline__ void split_bf16(float x, __nv_bfloat16& hi, __nv_bfloat16& lo) {
    hi = __float2bfloat16(x);
    lo = __float2bfloat16(x - __bfloat162float(hi));
}

// ==================== prep kernels ====================
// mask dtype detect+normalize (u8 vs 4-byte), plus zero the mu buffers.
__global__ void mask_norm_kernel(const unsigned char* __restrict__ m_raw)
{
    __shared__ int s_is_u8;
    int tid = threadIdx.x;
    if (tid == 0) s_is_u8 = 0;
    __syncthreads();
    for (int i = tid; i < 1024; i += blockDim.x)
        if (m_raw[4 * i + 1] != 0) atomicOr(&s_is_u8, 1);
    __syncthreads();
    const int is_u8 = s_is_u8;
    const unsigned int* m32 = reinterpret_cast<const unsigned int*>(m_raw);
    for (int i = tid; i < Bq * Tq; i += blockDim.x)
        g_mask[i] = is_u8 ? (m_raw[i] != 0) : (m32[i] != 0u);
    if (tid < 2 * Bq) ((float*)g_mu)[tid] = 0.0f;
}

// Split a fp32 array into bf16 hi/lo device globals (selected by `which`).
__global__ void prep_split_kernel(const float* __restrict__ src, int n, int which)
{
    __nv_bfloat16 *hi, *lo;
    switch (which) {
        case 0: hi = g_WihH0; lo = g_WihL0; break;
        case 1: hi = g_WhhH0; lo = g_WhhL0; break;
        case 2: hi = g_WihH1; lo = g_WihL1; break;
        case 3: hi = g_WhhH1; lo = g_WhhL1; break;
        default: hi = g_featH; lo = g_featL; break;
    }
    for (long long i = (long long)blockIdx.x * blockDim.x + threadIdx.x; i < n;
         i += (long long)gridDim.x * blockDim.x) {
        float x = src[i];
        __nv_bfloat16 h = __float2bfloat16(x);
        hi[i] = h;
        lo[i] = __float2bfloat16(x - __bfloat162float(h));
    }
}

// ==================== shared-memory layout ====================
// k16 tile rows padded to 24 bf16 (48B): 8-row x 4-kpair b32 fragment loads are
// conflict-free (r*12+t mod 32 covers all banks exactly once).
struct Stage {
    __align__(16) __nv_bfloat16 Ah[64 * 24];
    __align__(16) __nv_bfloat16 Al[64 * 24];
    __align__(16) __nv_bfloat16 Bh[64 * 24];
    __align__(16) __nv_bfloat16 Bl[64 * 24];
};
struct CellSmem {
    Stage stg[4];              // 4-stage cp.async pipeline (49,152 B)
    float gate[64 * 66];       // fused-epilogue gate buffer (pad 66 => 8B-aligned float2)
    float mu_s[64];
    unsigned char um_s[64];
};
#define CELL_SMEM_BYTES ((int)sizeof(CellSmem))

// ==================== low-level helpers ====================
__device__ __forceinline__ void cp16(void* dst, const void* src) {
    unsigned d = (unsigned)__cvta_generic_to_shared(dst);
    asm volatile("cp.async.cg.shared.global [%0], [%1], 16;\n" :: "r"(d), "l"(src));
}
__device__ __forceinline__ void cp_commit() { asm volatile("cp.async.commit_group;\n"); }
__device__ __forceinline__ void cp_wait2()  { asm volatile("cp.async.wait_group 2;\n" ::: "memory"); }

__device__ __forceinline__ void mma_bf16(float d[4], const unsigned a[4], const unsigned b[2]) {
    asm volatile(
        "mma.sync.aligned.m16n8k16.row.col.f32.bf16.bf16.f32 "
        "{%0,%1,%2,%3}, {%4,%5,%6,%7}, {%8,%9}, {%0,%1,%2,%3};\n"
        : "+f"(d[0]), "+f"(d[1]), "+f"(d[2]), "+f"(d[3])
        : "r"(a[0]), "r"(a[1]), "r"(a[2]), "r"(a[3]), "r"(b[0]), "r"(b[1]));
}

// Stage one k16 chunk: A tile = x[64b][16k] hi/lo, B tile = W[64n][16k] hi/lo.
// Each of 128 threads moves one (row, 16B-half) for all four buffers.
__device__ __forceinline__ void issue_stage(Stage* st,
    const __nv_bfloat16* xh, const __nv_bfloat16* xl, long long xstr, int kx,
    const __nv_bfloat16* wh, const __nv_bfloat16* wl, int ldW, int kw,
    int j0, int row, int half)
{
    int o = row * 24 + half * 8;
    long long xo = (long long)row * xstr + kx + half * 8;
    cp16(st->Ah + o, xh + xo);
    cp16(st->Al + o, xl + xo);
    int wrow = ((row >> 4) << 10) + j0 + (row & 15);   // (gate)*Hq + j0 + jj
    long long wo = (long long)wrow * ldW + kw + half * 8;
    cp16(st->Bh + o, wh + wo);
    cp16(st->Bl + o, wl + wo);
}

// One k16 chunk of the 64x64 CTA tile: per warp 2 m-tiles x 4 n-tiles, 3 split-mma each.
__device__ __forceinline__ void compute_chunk(const Stage* st, float acc[2][4][4],
                                              int warp_m, int warp_n, int grp, int tg)
{
    const char* Ah = (const char*)st->Ah;
    const char* Al = (const char*)st->Al;
    const char* Bh = (const char*)st->Bh;
    const char* Bl = (const char*)st->Bl;
    unsigned aH[2][4], aL[2][4], bH[4][2], bL[4][2];
#pragma unroll
    for (int mt = 0; mt < 2; mt++) {
        int r = (warp_m + mt * 16 + grp) * 48 + tg * 4;
        aH[mt][0] = *(const unsigned*)(Ah + r);
        aH[mt][1] = *(const unsigned*)(Ah + r + 8 * 48);
        aH[mt][2] = *(const unsigned*)(Ah + r + 16);
        aH[mt][3] = *(const unsigned*)(Ah + r + 8 * 48 + 16);
        aL[mt][0] = *(const unsigned*)(Al + r);
        aL[mt][1] = *(const unsigned*)(Al + r + 8 * 48);
        aL[mt][2] = *(const unsigned*)(Al + r + 16);
        aL[mt][3] = *(const unsigned*)(Al + r + 8 * 48 + 16);
    }
#pragma unroll
    for (int nt = 0; nt < 4; nt++) {
        int r = (warp_n + nt * 8 + grp) * 48 + tg * 4;
        bH[nt][0] = *(const unsigned*)(Bh + r);
        bH[nt][1] = *(const unsigned*)(Bh + r + 16);
        bL[nt][0] = *(const unsigned*)(Bl + r);
        bL[nt][1] = *(const unsigned*)(Bl + r + 16);
    }
#pragma unroll
    for (int mt = 0; mt < 2; mt++)
#pragma unroll
        for (int nt = 0; nt < 4; nt++) {
            mma_bf16(acc[mt][nt], aH[mt], bH[nt]);   // hi*hi
            mma_bf16(acc[mt][nt], aH[mt], bL[nt]);   // hi*lo
            mma_bf16(acc[mt][nt], aL[mt], bH[nt]);   // lo*hi  (lo*lo dropped)
        }
}

// Pipelined GEMM phase over nch k16 chunks (4-stage cp.async double-buffer).
__device__ __forceinline__ void run_phase(CellSmem* sm, float acc[2][4][4],
    const __nv_bfloat16* xh, const __nv_bfloat16* xl, long long xstr,
    const __nv_bfloat16* wh, const __nv_bfloat16* wl, int ldW,
    int nch, int j0, int row, int half, int warp_m, int warp_n, int grp, int tg)
{
    if (nch == 0) return;
    __syncthreads();                       // protect stage reuse across phases
    int npre = nch < 3 ? nch : 3;
    for (int i = 0; i < npre; i++) {
        issue_stage(&sm->stg[i], xh, xl, xstr, i * 16, wh, wl, ldW, i * 16, j0, row, half);
        cp_commit();
    }
    for (int c = 0; c < nch; c++) {
        cp_wait2();
        __syncthreads();
        int nc = c + 3;
        if (nc < nch) {
            issue_stage(&sm->stg[nc & 3], xh, xl, xstr, nc * 16, wh, wl, ldW, nc * 16,
                        j0, row, half);
            cp_commit();
        }
        compute_chunk(&sm->stg[c & 3], acc, warp_m, warp_n, grp, tg);
    }
}

// Fused epilogue: fragments -> smem gate buffer -> LSTM cell update -> split-h store
// + per-CTA partial of mu = hp . mu_w (layer selects even/odd mu_w entries).
__device__ __forceinline__ void lstm_epilogue(CellSmem* sm, float acc[2][4][4],
    const float* __restrict__ bih, const float* __restrict__ bhh,
    float* __restrict__ cst, __nv_bfloat16* __restrict__ hH, __nv_bfloat16* __restrict__ hL,
    const float* __restrict__ mu_w, int layer, int t, int b0, int j0,
    int tid, int warp_m, int warp_n, int grp, int tg)
{
#pragma unroll
    for (int mt = 0; mt < 2; mt++)
#pragma unroll
        for (int nt = 0; nt < 4; nt++) {
            int b = warp_m + mt * 16 + grp;
            int n = warp_n + nt * 8 + tg * 2;
            *(float2*)&sm->gate[b * 66 + n] = make_float2(acc[mt][nt][0], acc[mt][nt][1]);
            *(float2*)&sm->gate[(b + 8) * 66 + n] = make_float2(acc[mt][nt][2], acc[mt][nt][3]);
        }
    __syncthreads();
    int b = tid >> 1, hf = tid & 1;
    int bg = b0 + b;
    float p = 0.0f;
#pragma unroll
    for (int q = 0; q < 8; q++) {
        int jj = hf * 8 + q, j = j0 + jj;
        float gi = sm->gate[b * 66 + jj]      + bih[j]          + bhh[j];
        float gf = sm->gate[b * 66 + 16 + jj] + bih[Hq + j]     + bhh[Hq + j];
        float gg = sm->gate[b * 66 + 32 + jj] + bih[2 * Hq + j] + bhh[2 * Hq + j];
        float go = sm->gate[b * 66 + 48 + jj] + bih[3 * Hq + j] + bhh[3 * Hq + j];
        float cp = (t == 0) ? 0.0f : cst[bg * Hq + j];
        float c = sigmoidf_(gf) * cp + sigmoidf_(gi) * tanhf(gg);
        float h = sigmoidf_(go) * tanhf(c);
        cst[bg * Hq + j] = c;
        __nv_bfloat16 hh, hl;
        split_bf16(h, hh, hl);
        long long hidx = ((long long)t * Bq + bg) * Hq + j;
        hH[hidx] = hh;
        hL[hidx] = hl;
        p = fmaf(h, mu_w[2 * j + layer], p);
    }
    p += __shfl_xor_sync(0xffffffffu, p, 1);
    if (hf == 0) atomicAdd(&g_mu[t & 1][bg], p);
}

// ==================== layer-0 cell ====================
__global__ void __launch_bounds__(128) cell0_kernel(
    const float* __restrict__ emb,
    const float* __restrict__ W_tgt, const float* __restrict__ b_tgt,
    const float* __restrict__ b_ih0, const float* __restrict__ b_hh0,
    const float* __restrict__ mu_w, const float* __restrict__ mu_b, int t)
{
    extern __shared__ char smraw[];
    CellSmem* sm = (CellSmem*)smraw;
    int tid = threadIdx.x, lane = tid & 31, wid = tid >> 5;
    int grp = lane >> 2, tg = lane & 3;
    int warp_m = (wid >> 1) * 32, warp_n = (wid & 1) * 32;
    int row = tid >> 1, half = tid & 1;
    int jb = blockIdx.x & 63, b0 = (blockIdx.x >> 6) * 64, j0 = jb * 16;

    float acc[2][4][4];
#pragma unroll
    for (int i = 0; i < 2; i++)
#pragma unroll
        for (int j = 0; j < 4; j++)
#pragma unroll
            for (int k = 0; k < 4; k++) acc[i][j][k] = 0.0f;

    // phase 1: feat (K=512), x row b -> feat[b0+b][t][*], stride T*F elements
    {
        long long off = ((long long)b0 * Tq + t) * Fq;
        run_phase(sm, acc, g_featH + off, g_featL + off, (long long)Tq * Fq,
                  g_WihH0, g_WihL0, IN0q, Fq / 16, j0, row, half, warp_m, warp_n, grp, tg);
    }
    // phase 2: h0(t-1) (K=1024), skip at t=0
    if (t > 0) {
        long long off = ((long long)(t - 1) * Bq + b0) * Hq;
        run_phase(sm, acc, g_h0h + off, g_h0l + off, (long long)Hq,
                  g_WhhH0, g_WhhL0, Hq, Hq / 16, j0, row, half, warp_m, warp_n, grp, tg);
    }
    // phase 3: label segment (K=64), x built on the fly from mask/mu feedback
    if (tid < 64) {
        int bg = b0 + tid;
        int um = (t > 0) && g_mask[bg * Tq + t];
        sm->um_s[tid] = (unsigned char)um;
        sm->mu_s[tid] = um ? (g_mu[(t - 1) & 1][bg] + mu_b[0]) : 0.0f;
    }
    __syncthreads();
    for (int lc = 0; lc < 4; lc++) {
#pragma unroll
        for (int i = 0; i < 8; i++) {         // x tile: 64x16 values
            int id = i * 128 + tid;
            int r = id >> 4, kk = id & 15, e = lc * 16 + kk;
            float v = sm->um_s[r] ? fmaf(sm->mu_s[r], W_tgt[e], b_tgt[e])
                                  : emb[((long long)(b0 + r) * Tq + t) * Eq + e];
            __nv_bfloat16 hi, lo;
            split_bf16(v, hi, lo);
            sm->stg[0].Ah[r * 24 + kk] = hi;
            sm->stg[0].Al[r * 24 + kk] = lo;
        }
#pragma unroll
        for (int i = 0; i < 16; i++) {        // W tile: 64x16 x (hi,lo)
            int id = i * 128 + tid;
            int spl = id >> 10, rem = id & 1023;
            int n = rem >> 4, kk = rem & 15;
            int wrow = ((n >> 4) << 10) + j0 + (n & 15);
            long long off = (long long)wrow * IN0q + Fq + lc * 16 + kk;
            if (spl) sm->stg[0].Bl[n * 24 + kk] = g_WihL0[off];
            else     sm->stg[0].Bh[n * 24 + kk] = g_WihH0[off];
        }
        __syncthreads();
        compute_chunk(&sm->stg[0], acc, warp_m, warp_n, grp, tg);
        __syncthreads();
    }

    lstm_epilogue(sm, acc, b_ih0, b_hh0, g_c0, g_h0h, g_h0l, mu_w, 0,
                  t, b0, j0, tid, warp_m, warp_n, grp, tg);
}

// ==================== layer-1 cell ====================
__global__ void __launch_bounds__(128) cell1_kernel(
    const float* __restrict__ b_ih1, const float* __restrict__ b_hh1,
    const float* __restrict__ mu_w, int t)
{
    extern __shared__ char smraw[];
    CellSmem* sm = (CellSmem*)smraw;
    int tid = threadIdx.x, lane = tid & 31, wid = tid >> 5;
    int grp = lane >> 2, tg = lane & 3;
    int warp_m = (wid >> 1) * 32, warp_n = (wid & 1) * 32;
    int row = tid >> 1, half = tid & 1;
    int jb = blockIdx.x & 63, b0 = (blockIdx.x >> 6) * 64, j0 = jb * 16;

    // Re-zero the OTHER mu buffer (already consumed by cell0 of this step);
    // this kernel's atomics target g_mu[t&1] only, so no overlap.
    if (blockIdx.x == 0 && tid < Bq) g_mu[1 - (t & 1)][tid] = 0.0f;

    float acc[2][4][4];
#pragma unroll
    for (int i = 0; i < 2; i++)
#pragma unroll
        for (int j = 0; j < 4; j++)
#pragma unroll
            for (int k = 0; k < 4; k++) acc[i][j][k] = 0.0f;

    // phase 1: x = h0(t)  (written by cell0 this step)
    {
        long long off = ((long long)t * Bq + b0) * Hq;
        run_phase(sm, acc, g_h0h + off, g_h0l + off, (long long)Hq,
                  g_WihH1, g_WihL1, Hq, Hq / 16, j0, row, half, warp_m, warp_n, grp, tg);
    }
    // phase 2: x = h1(t-1), skip at t=0
    if (t > 0) {
        long long off = ((long long)(t - 1) * Bq + b0) * Hq;
        run_phase(sm, acc, g_h1h + off, g_h1l + off, (long long)Hq,
                  g_WhhH1, g_WhhL1, Hq, Hq / 16, j0, row, half, warp_m, warp_n, grp, tg);
    }

    lstm_epilogue(sm, acc, b_ih1, b_hh1, g_c1, g_h1h, g_h1l, mu_w, 1,
                  t, b0, j0, tid, warp_m, warp_n, grp, tg);
}

// ==================== final outputs ====================
__global__ void out_kernel(
    const float* __restrict__ mu_w, const float* __restrict__ mu_b,
    const float* __restrict__ sig_w, const float* __restrict__ sig_b,
    float* __restrict__ out)
{
    int t = blockIdx.x;
    int wid = threadIdx.x >> 5, lane = threadIdx.x & 31;
    const float2* mw2 = reinterpret_cast<const float2*>(mu_w);
    const float2* sw2 = reinterpret_cast<const float2*>(sig_w);
    for (int b = wid; b < Bq; b += 8) {
        long long base = ((long long)t * Bq + b) * Hq;
        float mp = 0.0f, sp = 0.0f;
        for (int h = lane; h < Hq; h += 32) {
            float a = __bfloat162float(g_h0h[base + h]) + __bfloat162float(g_h0l[base + h]);
            float c = __bfloat162float(g_h1h[base + h]) + __bfloat162float(g_h1l[base + h]);
            float2 m = mw2[h];
            float2 s = sw2[h];
            mp = fmaf(a, m.x, fmaf(c, m.y, mp));
            sp = fmaf(a, s.x, fmaf(c, s.y, sp));
        }
#pragma unroll
        for (int o = 16; o; o >>= 1) {
            mp += __shfl_xor_sync(0xffffffffu, mp, o);
            sp += __shfl_xor_sync(0xffffffffu, sp, o);
        }
        if (lane == 0) {
            float mu = mp + mu_b[0];
            float sv = sp + sig_b[0];
            float sig = fmaxf(sv, 0.0f) + log1pf(expf(-fabsf(sv)));
            out[(b * Tq + t) * 2 + 0] = mu;
            out[(b * Tq + t) * 2 + 1] = sig;
        }
    }
}

// ==================== launch ====================
extern "C" void kernel_launch(void* const* d_in, const int* in_sizes, int n_in,
                              void* d_out, int out_size)
{
    const float* feat  = (const float*)d_in[0];
    const float* emb   = (const float*)d_in[1];
    const unsigned char* mask_raw = (const unsigned char*)d_in[2];
    const float* W_ih0 = (const float*)d_in[3];
    const float* W_hh0 = (const float*)d_in[4];
    const float* b_ih0 = (const float*)d_in[5];
    const float* b_hh0 = (const float*)d_in[6];
    const float* W_ih1 = (const float*)d_in[7];
    const float* W_hh1 = (const float*)d_in[8];
    const float* b_ih1 = (const float*)d_in[9];
    const float* b_hh1 = (const float*)d_in[10];
    const float* W_tgt = (const float*)d_in[11];
    const float* b_tgt = (const float*)d_in[12];
    const float* mu_w  = (const float*)d_in[13];
    const float* mu_b  = (const float*)d_in[14];
    const float* sig_w = (const float*)d_in[15];
    const float* sig_b = (const float*)d_in[16];
    float* out = (float*)d_out;

    cudaFuncSetAttribute(cell0_kernel, cudaFuncAttributeMaxDynamicSharedMemorySize,
                         CELL_SMEM_BYTES);
    cudaFuncSetAttribute(cell1_kernel, cudaFuncAttributeMaxDynamicSharedMemorySize,
                         CELL_SMEM_BYTES);

    mask_norm_kernel<<<1, 1024>>>(mask_raw);
    prep_split_kernel<<<1024, 256>>>(W_ih0, 4 * Hq * IN0q, 0);
    prep_split_kernel<<<1024, 256>>>(W_hh0, 4 * Hq * Hq, 1);
    prep_split_kernel<<<1024, 256>>>(W_ih1, 4 * Hq * Hq, 2);
    prep_split_kernel<<<1024, 256>>>(W_hh1, 4 * Hq * Hq, 3);
    prep_split_kernel<<<2048, 256>>>(feat, Bq * Tq * Fq, 4);

    for (int t = 0; t < Tq; ++t) {
        cell0_kernel<<<128, 128, CELL_SMEM_BYTES>>>(emb, W_tgt, b_tgt, b_ih0, b_hh0,
                                                    mu_w, mu_b, t);
        cell1_kernel<<<128, 128, CELL_SMEM_BYTES>>>(b_ih1, b_hh1, mu_w, t);
    }
    out_kernel<<<Tq, 256>>>(mu_w, mu_b, sig_w, sig_b, out);
}

// round 11
// speedup vs baseline: 2.1788x; 1.9642x over previous
#include <cuda_runtime.h>
#include <cuda_bf16.h>
#include <math.h>

// Problem constants
#define Bq 128
#define Tq 160
#define Fq 512
#define Eq 64
#define Hq 1024
#define IN0q (Fq + Eq)   // 576

// ==================== persistent device scratch (no allocs) ====================
__device__ __align__(256) __nv_bfloat16 g_WihH0[4 * Hq * IN0q];
__device__ __align__(256) __nv_bfloat16 g_WihL0[4 * Hq * IN0q];
__device__ __align__(256) __nv_bfloat16 g_WhhH0[4 * Hq * Hq];
__device__ __align__(256) __nv_bfloat16 g_WhhL0[4 * Hq * Hq];
__device__ __align__(256) __nv_bfloat16 g_WihH1[4 * Hq * Hq];
__device__ __align__(256) __nv_bfloat16 g_WihL1[4 * Hq * Hq];
__device__ __align__(256) __nv_bfloat16 g_WhhH1[4 * Hq * Hq];
__device__ __align__(256) __nv_bfloat16 g_WhhL1[4 * Hq * Hq];
__device__ __align__(256) __nv_bfloat16 g_featH[Bq * Tq * Fq];
__device__ __align__(256) __nv_bfloat16 g_featL[Bq * Tq * Fq];
__device__ __align__(256) __nv_bfloat16 g_h0h[Tq * Bq * Hq];
__device__ __align__(256) __nv_bfloat16 g_h0l[Tq * Bq * Hq];
__device__ __align__(256) __nv_bfloat16 g_h1h[Tq * Bq * Hq];
__device__ __align__(256) __nv_bfloat16 g_h1l[Tq * Bq * Hq];
__device__ float g_c0[Bq * Hq];
__device__ float g_c1[Bq * Hq];
__device__ float g_mu[2][Bq];
__device__ unsigned char g_mask[Bq * Tq];
__device__ unsigned g_bar_ctr;          // grid-barrier counter (monotonic per launch)

__device__ __forceinline__ float sigmoidf_(float x) { return 1.0f / (1.0f + expf(-x)); }

__device__ __forceinline__ void split_bf16(float x, __nv_bfloat16& hi, __nv_bfloat16& lo) {
    hi = __float2bfloat16(x);
    lo = __float2bfloat16(x - __bfloat162float(hi));
}

__device__ __forceinline__ unsigned s2u(const void* p) {
    return (unsigned)__cvta_generic_to_shared(p);
}

// ==================== prep kernels ====================
__global__ void mask_norm_kernel(const unsigned char* __restrict__ m_raw)
{
    __shared__ int s_is_u8;
    int tid = threadIdx.x;
    if (tid == 0) { s_is_u8 = 0; g_bar_ctr = 0u; }
    __syncthreads();
    for (int i = tid; i < 1024; i += blockDim.x)
        if (m_raw[4 * i + 1] != 0) atomicOr(&s_is_u8, 1);
    __syncthreads();
    const int is_u8 = s_is_u8;
    const unsigned int* m32 = reinterpret_cast<const unsigned int*>(m_raw);
    for (int i = tid; i < Bq * Tq; i += blockDim.x)
        g_mask[i] = is_u8 ? (m_raw[i] != 0) : (m32[i] != 0u);
    if (tid < 2 * Bq) ((float*)g_mu)[tid] = 0.0f;
}

__global__ void prep_split_kernel(const float* __restrict__ src, int n, int which)
{
    __nv_bfloat16 *hi, *lo;
    switch (which) {
        case 0: hi = g_WihH0; lo = g_WihL0; break;
        case 1: hi = g_WhhH0; lo = g_WhhL0; break;
        case 2: hi = g_WihH1; lo = g_WihL1; break;
        case 3: hi = g_WhhH1; lo = g_WhhL1; break;
        default: hi = g_featH; lo = g_featL; break;
    }
    for (long long i = (long long)blockIdx.x * blockDim.x + threadIdx.x; i < n;
         i += (long long)gridDim.x * blockDim.x) {
        float x = src[i];
        __nv_bfloat16 h = __float2bfloat16(x);
        hi[i] = h;
        lo[i] = __float2bfloat16(x - __bfloat162float(h));
    }
}

// ==================== shared-memory layout ====================
// k16 tile rows padded to 24 bf16 (48B): ldmatrix 8-row reads cover all 32 banks once.
struct Stage {
    __align__(16) __nv_bfloat16 Ah[64 * 24];
    __align__(16) __nv_bfloat16 Al[64 * 24];
    __align__(16) __nv_bfloat16 Bh[64 * 24];
    __align__(16) __nv_bfloat16 Bl[64 * 24];
};
struct CellSmem {
    Stage stg[4];              // 4-stage cp.async ring
    float gate[64 * 66];
    float mu_s[64];
    unsigned char um_s[64];
};
#define CELL_SMEM_BYTES ((int)sizeof(CellSmem))

// ==================== low-level helpers ====================
__device__ __forceinline__ void cp16(void* dst, const void* src) {
    unsigned d = (unsigned)__cvta_generic_to_shared(dst);
    asm volatile("cp.async.cg.shared.global [%0], [%1], 16;\n" :: "r"(d), "l"(src));
}
__device__ __forceinline__ void cp_commit() { asm volatile("cp.async.commit_group;\n"); }
__device__ __forceinline__ void cp_wait2()  { asm volatile("cp.async.wait_group 2;\n" ::: "memory"); }

__device__ __forceinline__ void mma_bf16(float d[4], const unsigned a[4], const unsigned b[2]) {
    asm volatile(
        "mma.sync.aligned.m16n8k16.row.col.f32.bf16.bf16.f32 "
        "{%0,%1,%2,%3}, {%4,%5,%6,%7}, {%8,%9}, {%0,%1,%2,%3};\n"
        : "+f"(d[0]), "+f"(d[1]), "+f"(d[2]), "+f"(d[3])
        : "r"(a[0]), "r"(a[1]), "r"(a[2]), "r"(a[3]), "r"(b[0]), "r"(b[1]));
}
__device__ __forceinline__ void ldsm_x4(unsigned r[4], unsigned addr) {
    asm volatile("ldmatrix.sync.aligned.m8n8.x4.shared.b16 {%0,%1,%2,%3}, [%4];"
                 : "=r"(r[0]), "=r"(r[1]), "=r"(r[2]), "=r"(r[3]) : "r"(addr));
}
__device__ __forceinline__ void ldsm_x2(unsigned r[2], unsigned addr) {
    asm volatile("ldmatrix.sync.aligned.m8n8.x2.shared.b16 {%0,%1}, [%2];"
                 : "=r"(r[0]), "=r"(r[1]) : "r"(addr));
}

// Software grid barrier: all 128 CTAs co-resident (grid <= SM count).
__device__ __forceinline__ void grid_barrier(unsigned target)
{
    __syncthreads();
    if (threadIdx.x == 0) {
        asm volatile("red.release.gpu.add.u32 [%0], %1;"
                     :: "l"(&g_bar_ctr), "r"(1u) : "memory");
        unsigned v;
        do {
            asm volatile("ld.acquire.gpu.b32 %0, [%1];"
                         : "=r"(v) : "l"(&g_bar_ctr) : "memory");
        } while (v < target);
    }
    __syncthreads();
}

// Stage one k16 chunk. 256 threads: sel=0 (tid<128) moves A hi/lo, sel=1 moves B hi/lo.
__device__ __forceinline__ void issue_stage(Stage* st,
    const __nv_bfloat16* xh, const __nv_bfloat16* xl, long long xstr,
    const __nv_bfloat16* wh, const __nv_bfloat16* wl, int ldW, int k,
    int j0, int row, int half, int sel)
{
    int o = row * 24 + half * 8;
    if (sel == 0) {
        long long xo = (long long)row * xstr + k + half * 8;
        cp16(st->Ah + o, xh + xo);
        cp16(st->Al + o, xl + xo);
    } else {
        int wrow = ((row >> 4) << 10) + j0 + (row & 15);   // gate*Hq + j0 + jj
        long long wo = (long long)wrow * ldW + k + half * 8;
        cp16(st->Bh + o, wh + wo);
        cp16(st->Bl + o, wl + wo);
    }
}

// One k16 chunk, per-warp 32x16 subtile: 8 LDSM + 12 MMA (3-term bf16 split).
__device__ __forceinline__ void compute_chunk(const Stage* st, float acc[2][2][4],
                                              int warp_m, int warp_n, int lane)
{
    unsigned r8 = lane & 7;
    unsigned aoff = ((lane >> 3) & 1) * (8 * 48) + r8 * 48 + ((lane >> 4) & 1) * 16;
    unsigned boff = r8 * 48 + ((lane >> 3) & 1) * 16;
    unsigned ah = s2u(st->Ah), al = s2u(st->Al), bh = s2u(st->Bh), bl = s2u(st->Bl);
    unsigned aH[2][4], aL[2][4], bH[2][2], bL[2][2];
#pragma unroll
    for (int mt = 0; mt < 2; mt++) {
        unsigned base = (unsigned)(warp_m + mt * 16) * 48 + aoff;
        ldsm_x4(aH[mt], ah + base);
        ldsm_x4(aL[mt], al + base);
    }
#pragma unroll
    for (int nt = 0; nt < 2; nt++) {
        unsigned base = (unsigned)(warp_n + nt * 8) * 48 + boff;
        ldsm_x2(bH[nt], bh + base);
        ldsm_x2(bL[nt], bl + base);
    }
#pragma unroll
    for (int mt = 0; mt < 2; mt++)
#pragma unroll
        for (int nt = 0; nt < 2; nt++) {
            mma_bf16(acc[mt][nt], aH[mt], bH[nt]);   // hi*hi
            mma_bf16(acc[mt][nt], aH[mt], bL[nt]);   // hi*lo
            mma_bf16(acc[mt][nt], aL[mt], bH[nt]);   // lo*hi
        }
}

// Pipelined GEMM phase. Empty commit groups keep committed-count arithmetic exact,
// so wait_group(2) at iteration c always guarantees chunk c's data landed.
__device__ __forceinline__ void run_phase(CellSmem* sm, float acc[2][2][4],
    const __nv_bfloat16* xh, const __nv_bfloat16* xl, long long xstr,
    const __nv_bfloat16* wh, const __nv_bfloat16* wl, int ldW,
    int nch, int j0, int row, int half, int sel, int warp_m, int warp_n, int lane)
{
    __syncthreads();                        // all warps done with previous stage uses
#pragma unroll
    for (int i = 0; i < 3; i++) {
        if (i < nch)
            issue_stage(&sm->stg[i], xh, xl, xstr, wh, wl, ldW, i * 16, j0, row, half, sel);
        cp_commit();
    }
    for (int c = 0; c < nch; c++) {
        cp_wait2();
        __syncthreads();
        int nc = c + 3;
        if (nc < nch)
            issue_stage(&sm->stg[nc & 3], xh, xl, xstr, wh, wl, ldW, nc * 16, j0, row, half, sel);
        cp_commit();
        compute_chunk(&sm->stg[c & 3], acc, warp_m, warp_n, lane);
    }
}

// Fused epilogue: fragments -> gate smem -> LSTM cell -> split-h store + mu partial.
__device__ __forceinline__ void lstm_epilogue(CellSmem* sm, float acc[2][2][4],
    const float* __restrict__ bih, const float* __restrict__ bhh,
    float* __restrict__ cst, __nv_bfloat16* __restrict__ hH, __nv_bfloat16* __restrict__ hL,
    const float* __restrict__ mu_w, int layer, int t, int b0, int j0,
    int tid, int warp_m, int warp_n)
{
    int lane = tid & 31, grp = lane >> 2, tg = lane & 3;
#pragma unroll
    for (int mt = 0; mt < 2; mt++)
#pragma unroll
        for (int nt = 0; nt < 2; nt++) {
            int b = warp_m + mt * 16 + grp;
            int n = warp_n + nt * 8 + tg * 2;
            *(float2*)&sm->gate[b * 66 + n] = make_float2(acc[mt][nt][0], acc[mt][nt][1]);
            *(float2*)&sm->gate[(b + 8) * 66 + n] = make_float2(acc[mt][nt][2], acc[mt][nt][3]);
        }
    __syncthreads();
    int b = tid >> 2, q4 = tid & 3;
    int bg = b0 + b;
    float p = 0.0f;
#pragma unroll
    for (int q = 0; q < 4; q++) {
        int jj = q4 * 4 + q, j = j0 + jj;
        float gi = sm->gate[b * 66 + jj]      + bih[j]          + bhh[j];
        float gf = sm->gate[b * 66 + 16 + jj] + bih[Hq + j]     + bhh[Hq + j];
        float gg = sm->gate[b * 66 + 32 + jj] + bih[2 * Hq + j] + bhh[2 * Hq + j];
        float go = sm->gate[b * 66 + 48 + jj] + bih[3 * Hq + j] + bhh[3 * Hq + j];
        float cp = (t == 0) ? 0.0f : cst[bg * Hq + j];
        float c = sigmoidf_(gf) * cp + sigmoidf_(gi) * tanhf(gg);
        float h = sigmoidf_(go) * tanhf(c);
        cst[bg * Hq + j] = c;
        __nv_bfloat16 hh, hl;
        split_bf16(h, hh, hl);
        long long hidx = ((long long)t * Bq + bg) * Hq + j;
        hH[hidx] = hh;
        hL[hidx] = hl;
        p = fmaf(h, mu_w[2 * j + layer], p);
    }
    p += __shfl_xor_sync(0xffffffffu, p, 1);
    p += __shfl_xor_sync(0xffffffffu, p, 2);
    if (q4 == 0) atomicAdd(&g_mu[t & 1][bg], p);
}

// ==================== fused persistent kernel: all 160 timesteps ====================
__global__ void __launch_bounds__(256, 1) deepar_fused_kernel(
    const float* __restrict__ emb,
    const float* __restrict__ W_tgt, const float* __restrict__ b_tgt,
    const float* __restrict__ b_ih0, const float* __restrict__ b_hh0,
    const float* __restrict__ b_ih1, const float* __restrict__ b_hh1,
    const float* __restrict__ mu_w, const float* __restrict__ mu_b)
{
    extern __shared__ char smraw[];
    CellSmem* sm = (CellSmem*)smraw;
    int tid = threadIdx.x, lane = tid & 31, wid = tid >> 5;
    int warp_m = (wid & 1) * 32, warp_n = (wid >> 1) * 16;
    int sel = tid >> 7, row = (tid >> 1) & 63, half = tid & 1;
    int jb = blockIdx.x & 63, b0 = (blockIdx.x >> 6) * 64, j0 = jb * 16;
    unsigned bartgt = 0;

    for (int t = 0; t < Tq; ++t) {
        float acc[2][2][4];
#pragma unroll
        for (int i = 0; i < 2; i++)
#pragma unroll
            for (int j = 0; j < 2; j++)
#pragma unroll
                for (int k = 0; k < 4; k++) acc[i][j][k] = 0.0f;

        // ---------------- cell0 ----------------
        {   // feat phase (K=512)
            long long off = ((long long)b0 * Tq + t) * Fq;
            run_phase(sm, acc, g_featH + off, g_featL + off, (long long)Tq * Fq,
                      g_WihH0, g_WihL0, IN0q, Fq / 16, j0, row, half, sel,
                      warp_m, warp_n, lane);
        }
        if (t > 0) {  // recurrent phase (K=1024)
            long long off = ((long long)(t - 1) * Bq + b0) * Hq;
            run_phase(sm, acc, g_h0h + off, g_h0l + off, (long long)Hq,
                      g_WhhH0, g_WhhL0, Hq, Hq / 16, j0, row, half, sel,
                      warp_m, warp_n, lane);
        }
        // label phase (K=64), x built from mask/mu feedback
        if (tid < 64) {
            int bg = b0 + tid;
            int um = (t > 0) && g_mask[bg * Tq + t];
            sm->um_s[tid] = (unsigned char)um;
            sm->mu_s[tid] = um ? (__ldcg(&g_mu[(t - 1) & 1][bg]) + mu_b[0]) : 0.0f;
        }
        __syncthreads();
        for (int lc = 0; lc < 4; lc++) {
#pragma unroll
            for (int i = 0; i < 4; i++) {
                int id = i * 256 + tid;
                int r = id >> 4, kk = id & 15, e = lc * 16 + kk;
                float v = sm->um_s[r] ? fmaf(sm->mu_s[r], W_tgt[e], b_tgt[e])
                                      : emb[((long long)(b0 + r) * Tq + t) * Eq + e];
                __nv_bfloat16 hi, lo;
                split_bf16(v, hi, lo);
                sm->stg[0].Ah[r * 24 + kk] = hi;
                sm->stg[0].Al[r * 24 + kk] = lo;
            }
#pragma unroll
            for (int i = 0; i < 8; i++) {
                int id = i * 256 + tid;
                int spl = id >> 10, rem = id & 1023;
                int n = rem >> 4, kk = rem & 15;
                int wrow = ((n >> 4) << 10) + j0 + (n & 15);
                long long off = (long long)wrow * IN0q + Fq + lc * 16 + kk;
                if (spl) sm->stg[0].Bl[n * 24 + kk] = g_WihL0[off];
                else     sm->stg[0].Bh[n * 24 + kk] = g_WihH0[off];
            }
            __syncthreads();
            compute_chunk(&sm->stg[0], acc, warp_m, warp_n, lane);
            __syncthreads();
        }
        lstm_epilogue(sm, acc, b_ih0, b_hh0, g_c0, g_h0h, g_h0l, mu_w, 0,
                      t, b0, j0, tid, warp_m, warp_n);
        bartgt += 128;
        grid_barrier(bartgt);        // h0(t) now visible to all CTAs

        // ---------------- cell1 ----------------
        // re-zero the already-consumed mu parity buffer (next atomics hit it at t+1)
        if (blockIdx.x == 0 && tid < Bq) g_mu[1 - (t & 1)][tid] = 0.0f;
#pragma unroll
        for (int i = 0; i < 2; i++)
#pragma unroll
            for (int j = 0; j < 2; j++)
#pragma unroll
                for (int k = 0; k < 4; k++) acc[i][j][k] = 0.0f;
        {   // input phase: x = h0(t)
            long long off = ((long long)t * Bq + b0) * Hq;
            run_phase(sm, acc, g_h0h + off, g_h0l + off, (long long)Hq,
                      g_WihH1, g_WihL1, Hq, Hq / 16, j0, row, half, sel,
                      warp_m, warp_n, lane);
        }
        if (t > 0) {  // recurrent phase: x = h1(t-1)
            long long off = ((long long)(t - 1) * Bq + b0) * Hq;
            run_phase(sm, acc, g_h1h + off, g_h1l + off, (long long)Hq,
                      g_WhhH1, g_WhhL1, Hq, Hq / 16, j0, row, half, sel,
                      warp_m, warp_n, lane);
        }
        lstm_epilogue(sm, acc, b_ih1, b_hh1, g_c1, g_h1h, g_h1l, mu_w, 1,
                      t, b0, j0, tid, warp_m, warp_n);
        bartgt += 128;
        grid_barrier(bartgt);        // h1(t) + mu(t) visible; step complete
    }
}

// ==================== final outputs ====================
__global__ void out_kernel(
    const float* __restrict__ mu_w, const float* __restrict__ mu_b,
    const float* __restrict__ sig_w, const float* __restrict__ sig_b,
    float* __restrict__ out)
{
    int t = blockIdx.x;
    int wid = threadIdx.x >> 5, lane = threadIdx.x & 31;
    const float2* mw2 = reinterpret_cast<const float2*>(mu_w);
    const float2* sw2 = reinterpret_cast<const float2*>(sig_w);
    for (int b = wid; b < Bq; b += 8) {
        long long base = ((long long)t * Bq + b) * Hq;
        float mp = 0.0f, sp = 0.0f;
        for (int h = lane; h < Hq; h += 32) {
            float a = __bfloat162float(g_h0h[base + h]) + __bfloat162float(g_h0l[base + h]);
            float c = __bfloat162float(g_h1h[base + h]) + __bfloat162float(g_h1l[base + h]);
            float2 m = mw2[h];
            float2 s = sw2[h];
            mp = fmaf(a, m.x, fmaf(c, m.y, mp));
            sp = fmaf(a, s.x, fmaf(c, s.y, sp));
        }
#pragma unroll
        for (int o = 16; o; o >>= 1) {
            mp += __shfl_xor_sync(0xffffffffu, mp, o);
            sp += __shfl_xor_sync(0xffffffffu, sp, o);
        }
        if (lane == 0) {
            float mu = mp + mu_b[0];
            float sv = sp + sig_b[0];
            float sig = fmaxf(sv, 0.0f) + log1pf(expf(-fabsf(sv)));
            out[(b * Tq + t) * 2 + 0] = mu;
            out[(b * Tq + t) * 2 + 1] = sig;
        }
    }
}

// ==================== launch ====================
extern "C" void kernel_launch(void* const* d_in, const int* in_sizes, int n_in,
                              void* d_out, int out_size)
{
    const float* feat  = (const float*)d_in[0];
    const float* emb   = (const float*)d_in[1];
    const unsigned char* mask_raw = (const unsigned char*)d_in[2];
    const float* W_ih0 = (const float*)d_in[3];
    const float* W_hh0 = (const float*)d_in[4];
    const float* b_ih0 = (const float*)d_in[5];
    const float* b_hh0 = (const float*)d_in[6];
    const float* W_ih1 = (const float*)d_in[7];
    const float* W_hh1 = (const float*)d_in[8];
    const float* b_ih1 = (const float*)d_in[9];
    const float* b_hh1 = (const float*)d_in[10];
    const float* W_tgt = (const float*)d_in[11];
    const float* b_tgt = (const float*)d_in[12];
    const float* mu_w  = (const float*)d_in[13];
    const float* mu_b  = (const float*)d_in[14];
    const float* sig_w = (const float*)d_in[15];
    const float* sig_b = (const float*)d_in[16];
    float* out = (float*)d_out;

    static int attr_set = 0;
    cudaFuncSetAttribute(deepar_fused_kernel, cudaFuncAttributeMaxDynamicSharedMemorySize,
                         CELL_SMEM_BYTES);
    (void)attr_set;

    mask_norm_kernel<<<1, 1024>>>(mask_raw);
    prep_split_kernel<<<1024, 256>>>(W_ih0, 4 * Hq * IN0q, 0);
    prep_split_kernel<<<1024, 256>>>(W_hh0, 4 * Hq * Hq, 1);
    prep_split_kernel<<<1024, 256>>>(W_ih1, 4 * Hq * Hq, 2);
    prep_split_kernel<<<1024, 256>>>(W_hh1, 4 * Hq * Hq, 3);
    prep_split_kernel<<<2048, 256>>>(feat, Bq * Tq * Fq, 4);

    deepar_fused_kernel<<<128, 256, CELL_SMEM_BYTES>>>(
        emb, W_tgt, b_tgt, b_ih0, b_hh0, b_ih1, b_hh1, mu_w, mu_b);

    out_kernel<<<Tq, 256>>>(mu_w, mu_b, sig_w, sig_b, out);
}